// round 14
// baseline (speedup 1.0000x reference)
#include <cuda_runtime.h>
#include <cuda_bf16.h>

#define FULL_MASK 0xFFFFFFFFu
#define NCHUNK 3           // S = 192 = 3 chunks * 64 samples (2 per lane, float2)

// One warp per ray; each lane owns 2 consecutive samples per chunk (float2).
// All loads front-batched (15 LDG.64 -> high MLP). Prefix product over
// per-lane pair products (5 shfl rounds x 3 interleaved chains). rgb weights
// are lane-local -> no gather shuffles. Carry chain fused into the store loop
// and alpha recomputed from survival to keep regs <= 51 (5 blocks/SM).
__global__ void __launch_bounds__(256, 5) nerf_render_kernel(
    const float* __restrict__ rgb,     // [N, S, 3]
    const float* __restrict__ sigma,   // [N, S]
    const float* __restrict__ z_vals,  // [N, S]
    const float* __restrict__ rays_d,  // [N, 3]
    float* __restrict__ out,           // flattened 7-tuple
    int N)
{
    const int S = 192;
    const int warp_id = (int)((blockIdx.x * blockDim.x + threadIdx.x) >> 5);
    const int lane    = threadIdx.x & 31;
    if (warp_id >= N) return;
    const int ray = warp_id;

    const size_t NS = (size_t)N * (size_t)S;
    float* out_rgb   = out;
    float* out_depth = out + (size_t)3 * N;
    float* out_acc   = out + (size_t)4 * N;
    float* out_w     = out + (size_t)5 * N;
    float* out_disp  = out + (size_t)5 * N + NS;
    float* out_trans = out + (size_t)6 * N + NS;
    float* out_alpha = out + (size_t)6 * N + 2 * NS;

    const float2* zr2  = (const float2*)(z_vals + (size_t)ray * S);
    const float2* sr2  = (const float2*)(sigma  + (size_t)ray * S);
    const float2* cr2  = (const float2*)(rgb    + (size_t)ray * S * 3);
    float2* wr2 = (float2*)(out_w     + (size_t)ray * S);
    float2* tr2 = (float2*)(out_trans + (size_t)ray * S);
    float2* ar2 = (float2*)(out_alpha + (size_t)ray * S);

    // ---------------- Phase A: batch ALL global loads (15 LDG.64) -----------
    float2 z[NCHUNK], sg[NCHUNK];
    #pragma unroll
    for (int c = 0; c < NCHUNK; c++) {
        z[c]  = __ldcs(zr2 + c * 32 + lane);   // samples 64c+2l, +1
        sg[c] = __ldcs(sr2 + c * 32 + lane);
    }
    // rgb: lane owns floats [192c + 6l .. 6l+5] = (r0,g0)(b0,r1)(g1,b1)
    float2 v[NCHUNK][3];
    #pragma unroll
    for (int c = 0; c < NCHUNK; c++) {
        #pragma unroll
        for (int k = 0; k < 3; k++)
            v[c][k] = __ldcs(cr2 + c * 96 + 3 * lane + k);
    }
    const float dx = rays_d[ray * 3 + 0];
    const float dy = rays_d[ray * 3 + 1];
    const float dz = rays_d[ray * 3 + 2];
    const float norm = sqrtf(dx * dx + dy * dy + dz * dz);

    // ---------------- Phase B: survival per pair ---------------------------
    float2 t[NCHUNK];
    #pragma unroll
    for (int c = 0; c < NCHUNK; c++) {
        // dist for elem 0 is register-local; elem 1 needs next lane's z.x
        float znext = __shfl_down_sync(FULL_MASK, z[c].x, 1);
        if (c < NCHUNK - 1) {
            float nxt0 = __shfl_sync(FULL_MASK, z[c + 1].x, 0);
            if (lane == 31) znext = nxt0;
        }
        const float dist0 = z[c].y - z[c].x;
        const float dist1 = (c == NCHUNK - 1 && lane == 31) ? 1e10f
                                                            : (znext - z[c].y);
        const float x0 = fmaxf(sg[c].x, 0.0f) * (dist0 * norm);
        const float x1 = fmaxf(sg[c].y, 0.0f) * (dist1 * norm);
        t[c].x = __expf(-x0);                 // survival = exp(-x); alpha = 1 - t
        t[c].y = __expf(-x1);
    }

    // ---------------- Phase C: scan of pair products (3 chains, ILP) --------
    float p[NCHUNK];
    #pragma unroll
    for (int c = 0; c < NCHUNK; c++) p[c] = t[c].x * t[c].y;

    #pragma unroll
    for (int off = 1; off < 32; off <<= 1) {
        #pragma unroll
        for (int c = 0; c < NCHUNK; c++) {
            float q = __shfl_up_sync(FULL_MASK, p[c], off);
            if (lane >= off) p[c] *= q;
        }
    }
    float excl[NCHUNK], tot[NCHUNK];
    #pragma unroll
    for (int c = 0; c < NCHUNK; c++) {
        tot[c]  = __shfl_sync(FULL_MASK, p[c], 31);
        excl[c] = __shfl_up_sync(FULL_MASK, p[c], 1);
        if (lane == 0) excl[c] = 1.0f;
    }

    // ------- Phase D+E fused: carry chain, weights, stores, accumulation ----
    float accR = 0.f, accG = 0.f, accB = 0.f, accD = 0.f, accA = 0.f;
    float carry = 1.0f;

    #pragma unroll
    for (int c = 0; c < NCHUNK; c++) {
        float2 trans;
        trans.x = carry * excl[c];
        trans.y = trans.x * t[c].x;
        carry *= tot[c];

        float2 alpha;
        alpha.x = 1.0f - t[c].x;
        alpha.y = 1.0f - t[c].y;

        float2 w;
        w.x = alpha.x * trans.x;
        w.y = alpha.y * trans.y;

        __stcs(wr2 + c * 32 + lane, w);
        __stcs(tr2 + c * 32 + lane, trans);
        __stcs(ar2 + c * 32 + lane, alpha);

        accD += w.x * z[c].x + w.y * z[c].y;
        accA += w.x + w.y;

        // lane-local rgb: (r0,g0)(b0,r1)(g1,b1) — no shuffles
        accR += w.x * v[c][0].x + w.y * v[c][1].y;
        accG += w.x * v[c][0].y + w.y * v[c][2].x;
        accB += w.x * v[c][1].x + w.y * v[c][2].y;
    }

    // warp reduce the 5 scalars
    #pragma unroll
    for (int off = 16; off > 0; off >>= 1) {
        accR += __shfl_down_sync(FULL_MASK, accR, off);
        accG += __shfl_down_sync(FULL_MASK, accG, off);
        accB += __shfl_down_sync(FULL_MASK, accB, off);
        accD += __shfl_down_sync(FULL_MASK, accD, off);
        accA += __shfl_down_sync(FULL_MASK, accA, off);
    }

    if (lane == 0) {
        out_rgb[ray * 3 + 0] = accR;
        out_rgb[ray * 3 + 1] = accG;
        out_rgb[ray * 3 + 2] = accB;
        out_depth[ray] = accD;
        out_acc[ray]   = accA;
        out_disp[ray]  = 1.0f / fmaxf(1e-10f, accD / accA);
    }
}

extern "C" void kernel_launch(void* const* d_in, const int* in_sizes, int n_in,
                              void* d_out, int out_size) {
    const float* rgb    = (const float*)d_in[0];
    const float* sigma  = (const float*)d_in[1];
    const float* z_vals = (const float*)d_in[2];
    const float* rays_d = (const float*)d_in[3];
    float* out = (float*)d_out;

    const int N = in_sizes[3] / 3;          // 65536

    const int threads = 256;                // 8 warps = 8 rays / block
    const int blocks = (N * 32) / threads;  // 8192
    nerf_render_kernel<<<blocks, threads>>>(rgb, sigma, z_vals, rays_d, out, N);
}